// round 1
// baseline (speedup 1.0000x reference)
#include <cuda_runtime.h>
#include <math.h>

#define N_NODES   100000
#define N_EDGES   1600000
#define IN_F      256
#define OUT_TOT   128          // 4 heads * 32 feats
#define NEG_SLOPE 0.2f

// ---------------- scratch (static device memory; no allocations) -------------
__device__ __align__(16) float g_feat_src[(size_t)N_NODES * OUT_TOT]; // 51.2 MB
__device__ __align__(16) float g_el[N_NODES * 4];
__device__ __align__(16) float g_er[N_NODES * 4];
__device__ __align__(16) float g_e_tmp[(size_t)N_EDGES * 4];          // 25.6 MB
__device__ __align__(16) float g_csr_e[(size_t)N_EDGES * 4];          // 25.6 MB
__device__ int g_csr_src[N_EDGES];
__device__ int g_deg[N_NODES];
__device__ int g_row_ptr[N_NODES + 1];
__device__ int g_cursor[N_NODES];

// ---------------- 0: zero degree histogram -----------------------------------
__global__ void zero_deg_kernel() {
    int i = blockIdx.x * blockDim.x + threadIdx.x;
    if (i < N_NODES) g_deg[i] = 0;
}

// ---------------- 1: projection GEMM  feat[N,256] @ W^T[256,128] -------------
// Block tile 128x128, K-chunks of 16, 256 threads, 8x8 microtile (stride-16).
__global__ __launch_bounds__(256) void gemm_kernel(const float* __restrict__ A,
                                                   const float* __restrict__ W) {
    __shared__ float As[16][129];   // [k][m], padded
    __shared__ float Bs[16][129];   // [k][n], padded

    const int tid = threadIdx.x;
    const int bm  = blockIdx.x * 128;
    const int tx  = tid & 15;       // n-group
    const int ty  = tid >> 4;       // m-group

    float acc[8][8];
#pragma unroll
    for (int i = 0; i < 8; i++)
#pragma unroll
        for (int j = 0; j < 8; j++) acc[i][j] = 0.0f;

    for (int k0 = 0; k0 < IN_F; k0 += 16) {
#pragma unroll
        for (int l = 0; l < 2; l++) {
            int idx = tid + l * 256;        // 0..511
            int r   = idx >> 2;             // 0..127
            int kq  = (idx & 3) * 4;        // 0,4,8,12
            int grow = bm + r;
            float4 av = (grow < N_NODES)
                ? *(const float4*)&A[(size_t)grow * IN_F + k0 + kq]
                : make_float4(0.f, 0.f, 0.f, 0.f);
            As[kq + 0][r] = av.x; As[kq + 1][r] = av.y;
            As[kq + 2][r] = av.z; As[kq + 3][r] = av.w;
            float4 bv = *(const float4*)&W[(size_t)r * IN_F + k0 + kq];
            Bs[kq + 0][r] = bv.x; Bs[kq + 1][r] = bv.y;
            Bs[kq + 2][r] = bv.z; Bs[kq + 3][r] = bv.w;
        }
        __syncthreads();
#pragma unroll
        for (int k = 0; k < 16; k++) {
            float ra[8], rb[8];
#pragma unroll
            for (int i = 0; i < 8; i++) ra[i] = As[k][ty + i * 16];
#pragma unroll
            for (int j = 0; j < 8; j++) rb[j] = Bs[k][tx + j * 16];
#pragma unroll
            for (int i = 0; i < 8; i++)
#pragma unroll
                for (int j = 0; j < 8; j++) acc[i][j] += ra[i] * rb[j];
        }
        __syncthreads();
    }

#pragma unroll
    for (int i = 0; i < 8; i++) {
        int row = bm + ty + i * 16;
        if (row < N_NODES) {
#pragma unroll
            for (int j = 0; j < 8; j++)
                g_feat_src[(size_t)row * OUT_TOT + tx + j * 16] = acc[i][j];
        }
    }
}

// ---------------- 2: per-node attention logits el/er --------------------------
__global__ __launch_bounds__(256) void el_er_kernel(const float* __restrict__ attn_l,
                                                    const float* __restrict__ attn_r) {
    int gw   = (blockIdx.x * blockDim.x + threadIdx.x) >> 5;
    int lane = threadIdx.x & 31;
    if (gw >= N_NODES) return;
    const float* fs = &g_feat_src[(size_t)gw * OUT_TOT];
    float el[4], er[4];
#pragma unroll
    for (int h = 0; h < 4; h++) {
        float x = fs[h * 32 + lane];
        el[h] = x * attn_l[h * 32 + lane];
        er[h] = x * attn_r[h * 32 + lane];
    }
#pragma unroll
    for (int off = 16; off; off >>= 1) {
#pragma unroll
        for (int h = 0; h < 4; h++) {
            el[h] += __shfl_xor_sync(0xffffffffu, el[h], off);
            er[h] += __shfl_xor_sync(0xffffffffu, er[h], off);
        }
    }
    if (lane == 0) {
        ((float4*)g_el)[gw] = make_float4(el[0], el[1], el[2], el[3]);
        ((float4*)g_er)[gw] = make_float4(er[0], er[1], er[2], er[3]);
    }
}

// ---------------- 3: edge logits + LeakyReLU + degree histogram ---------------
__global__ void edge_kernel(const int* __restrict__ src, const int* __restrict__ dst,
                            const float* __restrict__ e_w,
                            const float* __restrict__ attn_ew) {
    int e = blockIdx.x * blockDim.x + threadIdx.x;
    if (e >= N_EDGES) return;
    int s = src[e], d = dst[e];
    float4 l  = ((const float4*)g_el)[s];
    float4 r  = ((const float4*)g_er)[d];
    float4 w0 = *(const float4*)&e_w[(size_t)e * 8];
    float4 w1 = *(const float4*)&e_w[(size_t)e * 8 + 4];
    float4 a0 = *(const float4*)&attn_ew[0];
    float4 a1 = *(const float4*)&attn_ew[4];
    float v0 = l.x + r.x + w0.x * a0.x + w0.y * a0.y;
    float v1 = l.y + r.y + w0.z * a0.z + w0.w * a0.w;
    float v2 = l.z + r.z + w1.x * a1.x + w1.y * a1.y;
    float v3 = l.w + r.w + w1.z * a1.z + w1.w * a1.w;
    v0 = v0 > 0.f ? v0 : NEG_SLOPE * v0;
    v1 = v1 > 0.f ? v1 : NEG_SLOPE * v1;
    v2 = v2 > 0.f ? v2 : NEG_SLOPE * v2;
    v3 = v3 > 0.f ? v3 : NEG_SLOPE * v3;
    ((float4*)g_e_tmp)[e] = make_float4(v0, v1, v2, v3);
    atomicAdd(&g_deg[d], 1);
}

// ---------------- 4: single-block exclusive scan -> row_ptr, cursor -----------
__global__ __launch_bounds__(1024) void scan_kernel() {
    __shared__ int ssum[1024];
    const int CHUNK = (N_NODES + 1023) / 1024;   // 98
    int t = threadIdx.x;
    int base = t * CHUNK;
    int s = 0;
    for (int j = 0; j < CHUNK; j++) {
        int idx = base + j;
        if (idx < N_NODES) s += g_deg[idx];
    }
    ssum[t] = s;
    __syncthreads();
    for (int off = 1; off < 1024; off <<= 1) {
        int v = (t >= off) ? ssum[t - off] : 0;
        __syncthreads();
        ssum[t] += v;
        __syncthreads();
    }
    int run = ssum[t] - s;   // exclusive prefix of this chunk
    for (int j = 0; j < CHUNK; j++) {
        int idx = base + j;
        if (idx < N_NODES) {
            g_row_ptr[idx] = run;
            g_cursor[idx]  = run;
            run += g_deg[idx];
        }
    }
    if (t == 1023) g_row_ptr[N_NODES] = run;
}

// ---------------- 5: scatter edges to CSR slots --------------------------------
__global__ void scatter_kernel(const int* __restrict__ src, const int* __restrict__ dst) {
    int e = blockIdx.x * blockDim.x + threadIdx.x;
    if (e >= N_EDGES) return;
    int d = dst[e];
    int pos = atomicAdd(&g_cursor[d], 1);
    g_csr_src[pos] = src[e];
    ((float4*)g_csr_e)[pos] = ((const float4*)g_e_tmp)[e];
}

// ---------------- 6: warp-per-node softmax + weighted aggregation + ELU --------
__global__ __launch_bounds__(256) void aggregate_kernel(float* __restrict__ out) {
    __shared__ float sp[8][128];   // per-warp: 32 edges x 4 heads of exp(e-m)
    __shared__ int   ssrc[8][32];
    int gw   = (blockIdx.x * blockDim.x + threadIdx.x) >> 5;
    int lane = threadIdx.x & 31;
    int wl   = threadIdx.x >> 5;
    if (gw >= N_NODES) return;
    int beg = g_row_ptr[gw], end = g_row_ptr[gw + 1];

    // pass 1: per-head max
    float m0 = -1e30f, m1 = -1e30f, m2 = -1e30f, m3 = -1e30f;
    for (int i = beg + lane; i < end; i += 32) {
        float4 ev = ((const float4*)g_csr_e)[i];
        m0 = fmaxf(m0, ev.x); m1 = fmaxf(m1, ev.y);
        m2 = fmaxf(m2, ev.z); m3 = fmaxf(m3, ev.w);
    }
#pragma unroll
    for (int off = 16; off; off >>= 1) {
        m0 = fmaxf(m0, __shfl_xor_sync(0xffffffffu, m0, off));
        m1 = fmaxf(m1, __shfl_xor_sync(0xffffffffu, m1, off));
        m2 = fmaxf(m2, __shfl_xor_sync(0xffffffffu, m2, off));
        m3 = fmaxf(m3, __shfl_xor_sync(0xffffffffu, m3, off));
    }

    // pass 2: unnormalized exp into smem, accumulate features + sums
    float s0 = 0.f, s1 = 0.f, s2 = 0.f, s3 = 0.f;
    float a0 = 0.f, a1 = 0.f, a2 = 0.f, a3 = 0.f;
    for (int c = beg; c < end; c += 32) {
        int i = c + lane;
        float4 p = make_float4(0.f, 0.f, 0.f, 0.f);
        if (i < end) {
            float4 ev = ((const float4*)g_csr_e)[i];
            p.x = __expf(ev.x - m0); p.y = __expf(ev.y - m1);
            p.z = __expf(ev.z - m2); p.w = __expf(ev.w - m3);
            s0 += p.x; s1 += p.y; s2 += p.z; s3 += p.w;
            ssrc[wl][lane] = g_csr_src[i];
        }
        ((float4*)sp[wl])[lane] = p;
        __syncwarp();
        int cnt = min(32, end - c);
        for (int j = 0; j < cnt; j++) {
            const float* fr = &g_feat_src[(size_t)ssrc[wl][j] * OUT_TOT];
            float w0 = sp[wl][j * 4 + 0];
            float w1 = sp[wl][j * 4 + 1];
            float w2 = sp[wl][j * 4 + 2];
            float w3 = sp[wl][j * 4 + 3];
            a0 += fr[       lane] * w0;
            a1 += fr[ 32 +  lane] * w1;
            a2 += fr[ 64 +  lane] * w2;
            a3 += fr[ 96 +  lane] * w3;
        }
        __syncwarp();
    }
#pragma unroll
    for (int off = 16; off; off >>= 1) {
        s0 += __shfl_xor_sync(0xffffffffu, s0, off);
        s1 += __shfl_xor_sync(0xffffffffu, s1, off);
        s2 += __shfl_xor_sync(0xffffffffu, s2, off);
        s3 += __shfl_xor_sync(0xffffffffu, s3, off);
    }
    float i0 = s0 > 0.f ? 1.f / s0 : 0.f;
    float i1 = s1 > 0.f ? 1.f / s1 : 0.f;
    float i2 = s2 > 0.f ? 1.f / s2 : 0.f;
    float i3 = s3 > 0.f ? 1.f / s3 : 0.f;
    a0 *= i0; a1 *= i1; a2 *= i2; a3 *= i3;

    size_t o = (size_t)gw * OUT_TOT;
    out[o +       lane] = a0 > 0.f ? a0 : expm1f(a0);
    out[o +  32 + lane] = a1 > 0.f ? a1 : expm1f(a1);
    out[o +  64 + lane] = a2 > 0.f ? a2 : expm1f(a2);
    out[o +  96 + lane] = a3 > 0.f ? a3 : expm1f(a3);
}

// ---------------- launch -------------------------------------------------------
extern "C" void kernel_launch(void* const* d_in, const int* in_sizes, int n_in,
                              void* d_out, int out_size) {
    const float* feat    = (const float*)d_in[0];
    const float* e_w     = (const float*)d_in[1];
    const int*   src     = (const int*)  d_in[2];
    const int*   dst     = (const int*)  d_in[3];
    const float* W_fc    = (const float*)d_in[4];
    const float* attn_l  = (const float*)d_in[5];
    const float* attn_r  = (const float*)d_in[6];
    const float* attn_ew = (const float*)d_in[7];
    float* out = (float*)d_out;

    zero_deg_kernel<<<(N_NODES + 255) / 256, 256>>>();
    gemm_kernel<<<(N_NODES + 127) / 128, 256>>>(feat, W_fc);
    el_er_kernel<<<((N_NODES * 32) + 255) / 256, 256>>>(attn_l, attn_r);
    edge_kernel<<<(N_EDGES + 255) / 256, 256>>>(src, dst, e_w, attn_ew);
    scan_kernel<<<1, 1024>>>();
    scatter_kernel<<<(N_EDGES + 255) / 256, 256>>>(src, dst);
    aggregate_kernel<<<((N_NODES * 32) + 255) / 256, 256>>>(out);
}

// round 3
// speedup vs baseline: 1.3667x; 1.3667x over previous
#include <cuda_runtime.h>
#include <cuda_bf16.h>
#include <stdint.h>
#include <math.h>

typedef unsigned int u32;

#define N_NODES   100000
#define N_EDGES   1600000
#define IN_F      256
#define OUT_TOT   128          // 4 heads * 32 feats
#define NEG_SLOPE 0.2f

// ---------------- scratch (static device memory; no allocations) -------------
__device__ __align__(16) float g_feat_src[(size_t)N_NODES * OUT_TOT]; // 51.2 MB
__device__ __align__(16) float g_el[N_NODES * 4];
__device__ __align__(16) float g_er[N_NODES * 4];
__device__ __align__(16) float g_csr_e[(size_t)N_EDGES * 4];          // 25.6 MB
__device__ int g_csr_src[N_EDGES];
__device__ int g_deg[N_NODES];
__device__ int g_row_ptr[N_NODES + 1];
__device__ int g_cursor[N_NODES];

// ---------------- helpers ------------------------------------------------------
__device__ __forceinline__ u32 pack_bf16(float a, float b) {
    __nv_bfloat162 t = __floats2bfloat162_rn(a, b);
    return *(u32*)&t;
}

#define MMA_BF16(c, a0, a1, a2, a3, b0, b1)                                     \
    asm volatile("mma.sync.aligned.m16n8k16.row.col.f32.bf16.bf16.f32 "         \
                 "{%0,%1,%2,%3}, {%4,%5,%6,%7}, {%8,%9}, {%0,%1,%2,%3};"        \
                 : "+f"((c)[0]), "+f"((c)[1]), "+f"((c)[2]), "+f"((c)[3])       \
                 : "r"(a0), "r"(a1), "r"(a2), "r"(a3), "r"(b0), "r"(b1))

// ---------------- 0: zero degree histogram -------------------------------------
__global__ void zero_deg_kernel() {
    int i = blockIdx.x * blockDim.x + threadIdx.x;
    if (i < N_NODES) g_deg[i] = 0;
}

// ---------------- 1: degree histogram -------------------------------------------
__global__ void deg_hist_kernel(const int* __restrict__ dst) {
    int e = blockIdx.x * blockDim.x + threadIdx.x;
    if (e < N_EDGES) atomicAdd(&g_deg[dst[e]], 1);
}

// ---------------- 2: projection GEMM via split-bf16 tensor cores ----------------
// C[128 nodes][128 outfeats] per block. Each input split x = hi + lo (bf16);
// accumulate hi*hi + hi*lo + lo*hi in fp32 => ~1e-5 relative accuracy.
__global__ __launch_bounds__(256) void gemm_mma_kernel(const float* __restrict__ A,
                                                       const float* __restrict__ W) {
    // smem as packed bf16x2 words; row stride 20 words = 80B (odd multiple of 16B -> conflict-free)
    __shared__ u32 Ah[128][20], Al[128][20], Bh[128][20], Bl[128][20];

    const int tid  = threadIdx.x;
    const int bm   = blockIdx.x * 128;
    const int lane = tid & 31;
    const int w    = tid >> 5;
    const int wr   = w >> 1;        // 0..3 (row tile of 32)
    const int wc   = w & 1;         // 0..1 (col tile of 64)
    const int g    = lane >> 2;     // 0..7
    const int tg   = lane & 3;      // 0..3

    float acc[2][8][4];
#pragma unroll
    for (int rt = 0; rt < 2; rt++)
#pragma unroll
        for (int nt = 0; nt < 8; nt++)
#pragma unroll
            for (int q = 0; q < 4; q++) acc[rt][nt][q] = 0.0f;

    for (int k0 = 0; k0 < IN_F; k0 += 32) {
#pragma unroll
        for (int l = 0; l < 4; l++) {
            int idx = tid + l * 256;       // 0..1023
            int r   = idx >> 3;            // 0..127
            int kq  = (idx & 7) * 4;       // 0..28
            int grow = bm + r;
            float4 av = (grow < N_NODES)
                ? *(const float4*)&A[(size_t)grow * IN_F + k0 + kq]
                : make_float4(0.f, 0.f, 0.f, 0.f);
            float hx = __bfloat162float(__float2bfloat16(av.x));
            float hy = __bfloat162float(__float2bfloat16(av.y));
            float hz = __bfloat162float(__float2bfloat16(av.z));
            float hw = __bfloat162float(__float2bfloat16(av.w));
            Ah[r][(kq >> 1) + 0] = pack_bf16(hx, hy);
            Ah[r][(kq >> 1) + 1] = pack_bf16(hz, hw);
            Al[r][(kq >> 1) + 0] = pack_bf16(av.x - hx, av.y - hy);
            Al[r][(kq >> 1) + 1] = pack_bf16(av.z - hz, av.w - hw);

            float4 bv = *(const float4*)&W[(size_t)r * IN_F + k0 + kq];
            float gx = __bfloat162float(__float2bfloat16(bv.x));
            float gy = __bfloat162float(__float2bfloat16(bv.y));
            float gz = __bfloat162float(__float2bfloat16(bv.z));
            float gw2 = __bfloat162float(__float2bfloat16(bv.w));
            Bh[r][(kq >> 1) + 0] = pack_bf16(gx, gy);
            Bh[r][(kq >> 1) + 1] = pack_bf16(gz, gw2);
            Bl[r][(kq >> 1) + 0] = pack_bf16(bv.x - gx, bv.y - gy);
            Bl[r][(kq >> 1) + 1] = pack_bf16(bv.z - gz, bv.w - gw2);
        }
        __syncthreads();

#pragma unroll
        for (int ks = 0; ks < 2; ks++) {
            int kb = ks * 8 + tg;     // uint32 col of fragment pair
#pragma unroll
            for (int rt = 0; rt < 2; rt++) {
                int rb = wr * 32 + rt * 16;
                u32 ah0 = Ah[rb + g    ][kb    ];
                u32 ah1 = Ah[rb + g + 8][kb    ];
                u32 ah2 = Ah[rb + g    ][kb + 4];
                u32 ah3 = Ah[rb + g + 8][kb + 4];
                u32 al0 = Al[rb + g    ][kb    ];
                u32 al1 = Al[rb + g + 8][kb    ];
                u32 al2 = Al[rb + g    ][kb + 4];
                u32 al3 = Al[rb + g + 8][kb + 4];
#pragma unroll
                for (int nt = 0; nt < 8; nt++) {
                    int nb = wc * 64 + nt * 8;
                    u32 bh0 = Bh[nb + g][kb    ];
                    u32 bh1 = Bh[nb + g][kb + 4];
                    u32 bl0 = Bl[nb + g][kb    ];
                    u32 bl1 = Bl[nb + g][kb + 4];
                    float* c = acc[rt][nt];
                    MMA_BF16(c, ah0, ah1, ah2, ah3, bh0, bh1);
                    MMA_BF16(c, ah0, ah1, ah2, ah3, bl0, bl1);
                    MMA_BF16(c, al0, al1, al2, al3, bh0, bh1);
                }
            }
        }
        __syncthreads();
    }

    // epilogue: c0,c1 -> (row g), c2,c3 -> (row g+8), cols tg*2,+1
#pragma unroll
    for (int rt = 0; rt < 2; rt++) {
        int r0 = bm + wr * 32 + rt * 16 + g;
#pragma unroll
        for (int nt = 0; nt < 8; nt++) {
            int cc = wc * 64 + nt * 8 + tg * 2;
            if (r0 < N_NODES)
                *(float2*)&g_feat_src[(size_t)r0 * OUT_TOT + cc] =
                    make_float2(acc[rt][nt][0], acc[rt][nt][1]);
            if (r0 + 8 < N_NODES)
                *(float2*)&g_feat_src[(size_t)(r0 + 8) * OUT_TOT + cc] =
                    make_float2(acc[rt][nt][2], acc[rt][nt][3]);
        }
    }
}

// ---------------- 3: per-node attention logits el/er ---------------------------
__global__ __launch_bounds__(256) void el_er_kernel(const float* __restrict__ attn_l,
                                                    const float* __restrict__ attn_r) {
    int gw   = (blockIdx.x * blockDim.x + threadIdx.x) >> 5;
    int lane = threadIdx.x & 31;
    if (gw >= N_NODES) return;
    const float* fs = &g_feat_src[(size_t)gw * OUT_TOT];
    float el[4], er[4];
#pragma unroll
    for (int h = 0; h < 4; h++) {
        float x = fs[h * 32 + lane];
        el[h] = x * attn_l[h * 32 + lane];
        er[h] = x * attn_r[h * 32 + lane];
    }
#pragma unroll
    for (int off = 16; off; off >>= 1) {
#pragma unroll
        for (int h = 0; h < 4; h++) {
            el[h] += __shfl_xor_sync(0xffffffffu, el[h], off);
            er[h] += __shfl_xor_sync(0xffffffffu, er[h], off);
        }
    }
    if (lane == 0) {
        ((float4*)g_el)[gw] = make_float4(el[0], el[1], el[2], el[3]);
        ((float4*)g_er)[gw] = make_float4(er[0], er[1], er[2], er[3]);
    }
}

// ---------------- 4: single-block exclusive scan -> row_ptr, cursor ------------
__global__ __launch_bounds__(1024) void scan_kernel() {
    __shared__ int ssum[1024];
    const int CHUNK = 100;            // 1000 active threads cover 100000 nodes
    int t = threadIdx.x;
    int base = t * CHUNK;
    int s = 0;
    if (base < N_NODES) {
        const int4* p = (const int4*)&g_deg[base];
#pragma unroll
        for (int j = 0; j < CHUNK / 4; j++) {
            int4 v = p[j];
            s += v.x + v.y + v.z + v.w;
        }
    }
    ssum[t] = s;
    __syncthreads();
    for (int off = 1; off < 1024; off <<= 1) {
        int v = (t >= off) ? ssum[t - off] : 0;
        __syncthreads();
        ssum[t] += v;
        __syncthreads();
    }
    if (base < N_NODES) {
        int run = ssum[t] - s;   // exclusive prefix of this chunk
        for (int j = 0; j < CHUNK; j++) {
            int idx = base + j;
            g_row_ptr[idx] = run;
            g_cursor[idx]  = run;
            run += g_deg[idx];
        }
    }
    if (t == 1023) g_row_ptr[N_NODES] = ssum[1023];
}

// ---------------- 5: fused edge logits + LeakyReLU + CSR scatter ----------------
__global__ void edge_scatter_kernel(const int* __restrict__ src, const int* __restrict__ dst,
                                    const float* __restrict__ e_w,
                                    const float* __restrict__ attn_ew) {
    int e = blockIdx.x * blockDim.x + threadIdx.x;
    if (e >= N_EDGES) return;
    int s = src[e], d = dst[e];
    float4 l  = ((const float4*)g_el)[s];
    float4 r  = ((const float4*)g_er)[d];
    float4 w0 = *(const float4*)&e_w[(size_t)e * 8];
    float4 w1 = *(const float4*)&e_w[(size_t)e * 8 + 4];
    float4 a0 = *(const float4*)&attn_ew[0];
    float4 a1 = *(const float4*)&attn_ew[4];
    float v0 = l.x + r.x + w0.x * a0.x + w0.y * a0.y;
    float v1 = l.y + r.y + w0.z * a0.z + w0.w * a0.w;
    float v2 = l.z + r.z + w1.x * a1.x + w1.y * a1.y;
    float v3 = l.w + r.w + w1.z * a1.z + w1.w * a1.w;
    v0 = v0 > 0.f ? v0 : NEG_SLOPE * v0;
    v1 = v1 > 0.f ? v1 : NEG_SLOPE * v1;
    v2 = v2 > 0.f ? v2 : NEG_SLOPE * v2;
    v3 = v3 > 0.f ? v3 : NEG_SLOPE * v3;
    int pos = atomicAdd(&g_cursor[d], 1);
    g_csr_src[pos] = s;
    ((float4*)g_csr_e)[pos] = make_float4(v0, v1, v2, v3);
}

// ---------------- 6: warp-per-node softmax + weighted aggregation + ELU ---------
// Lane l owns output columns [4l, 4l+4) => head = l>>3. One LDG.128 per edge/warp.
__global__ __launch_bounds__(256) void aggregate_kernel(float* __restrict__ out) {
    __shared__ float sp[8][128];   // per-warp: 32 edges x 4 heads of exp(e-m)
    __shared__ int   ssrc[8][32];
    int gw   = (blockIdx.x * blockDim.x + threadIdx.x) >> 5;
    int lane = threadIdx.x & 31;
    int wl   = threadIdx.x >> 5;
    if (gw >= N_NODES) return;
    int beg = g_row_ptr[gw], end = g_row_ptr[gw + 1];
    int head = lane >> 3;

    // pass 1: per-head max
    float m0 = -1e30f, m1 = -1e30f, m2 = -1e30f, m3 = -1e30f;
    for (int i = beg + lane; i < end; i += 32) {
        float4 ev = ((const float4*)g_csr_e)[i];
        m0 = fmaxf(m0, ev.x); m1 = fmaxf(m1, ev.y);
        m2 = fmaxf(m2, ev.z); m3 = fmaxf(m3, ev.w);
    }
#pragma unroll
    for (int off = 16; off; off >>= 1) {
        m0 = fmaxf(m0, __shfl_xor_sync(0xffffffffu, m0, off));
        m1 = fmaxf(m1, __shfl_xor_sync(0xffffffffu, m1, off));
        m2 = fmaxf(m2, __shfl_xor_sync(0xffffffffu, m2, off));
        m3 = fmaxf(m3, __shfl_xor_sync(0xffffffffu, m3, off));
    }

    // pass 2: unnormalized exp into smem; gather full feat row per edge (LDG.128)
    float s0 = 0.f, s1 = 0.f, s2 = 0.f, s3 = 0.f;
    float4 a = make_float4(0.f, 0.f, 0.f, 0.f);
    for (int c = beg; c < end; c += 32) {
        int i = c + lane;
        float4 p = make_float4(0.f, 0.f, 0.f, 0.f);
        if (i < end) {
            float4 ev = ((const float4*)g_csr_e)[i];
            p.x = __expf(ev.x - m0); p.y = __expf(ev.y - m1);
            p.z = __expf(ev.z - m2); p.w = __expf(ev.w - m3);
            s0 += p.x; s1 += p.y; s2 += p.z; s3 += p.w;
            ssrc[wl][lane] = g_csr_src[i];
        }
        ((float4*)sp[wl])[lane] = p;
        __syncwarp();
        int cnt = min(32, end - c);
        for (int j = 0; j < cnt; j++) {
            float4 fr = *(const float4*)&g_feat_src[(size_t)ssrc[wl][j] * OUT_TOT + lane * 4];
            float wgt = sp[wl][j * 4 + head];
            a.x += fr.x * wgt; a.y += fr.y * wgt;
            a.z += fr.z * wgt; a.w += fr.w * wgt;
        }
        __syncwarp();
    }
#pragma unroll
    for (int off = 16; off; off >>= 1) {
        s0 += __shfl_xor_sync(0xffffffffu, s0, off);
        s1 += __shfl_xor_sync(0xffffffffu, s1, off);
        s2 += __shfl_xor_sync(0xffffffffu, s2, off);
        s3 += __shfl_xor_sync(0xffffffffu, s3, off);
    }
    float invs;
    if      (head == 0) invs = s0 > 0.f ? 1.f / s0 : 0.f;
    else if (head == 1) invs = s1 > 0.f ? 1.f / s1 : 0.f;
    else if (head == 2) invs = s2 > 0.f ? 1.f / s2 : 0.f;
    else                invs = s3 > 0.f ? 1.f / s3 : 0.f;
    a.x *= invs; a.y *= invs; a.z *= invs; a.w *= invs;

    a.x = a.x > 0.f ? a.x : expm1f(a.x);
    a.y = a.y > 0.f ? a.y : expm1f(a.y);
    a.z = a.z > 0.f ? a.z : expm1f(a.z);
    a.w = a.w > 0.f ? a.w : expm1f(a.w);
    *(float4*)&out[(size_t)gw * OUT_TOT + lane * 4] = a;
}

// ---------------- launch --------------------------------------------------------
extern "C" void kernel_launch(void* const* d_in, const int* in_sizes, int n_in,
                              void* d_out, int out_size) {
    const float* feat    = (const float*)d_in[0];
    const float* e_w     = (const float*)d_in[1];
    const int*   src     = (const int*)  d_in[2];
    const int*   dst     = (const int*)  d_in[3];
    const float* W_fc    = (const float*)d_in[4];
    const float* attn_l  = (const float*)d_in[5];
    const float* attn_r  = (const float*)d_in[6];
    const float* attn_ew = (const float*)d_in[7];
    float* out = (float*)d_out;

    zero_deg_kernel<<<(N_NODES + 255) / 256, 256>>>();
    deg_hist_kernel<<<(N_EDGES + 255) / 256, 256>>>(dst);
    gemm_mma_kernel<<<(N_NODES + 127) / 128, 256>>>(feat, W_fc);
    el_er_kernel<<<((N_NODES * 32) + 255) / 256, 256>>>(attn_l, attn_r);
    scan_kernel<<<1, 1024>>>();
    edge_scatter_kernel<<<(N_EDGES + 255) / 256, 256>>>(src, dst, e_w, attn_ew);
    aggregate_kernel<<<((N_NODES * 32) + 255) / 256, 256>>>(out);
}

// round 4
// speedup vs baseline: 1.4512x; 1.0618x over previous
#include <cuda_runtime.h>
#include <cuda_bf16.h>
#include <stdint.h>
#include <math.h>

typedef unsigned int u32;

#define N_NODES   100000
#define N_EDGES   1600000
#define IN_F      256
#define OUT_TOT   128          // 4 heads * 32 feats
#define NEG_SLOPE 0.2f

// ---------------- scratch (static device memory; no allocations) -------------
__device__ __align__(16) float g_feat_src[(size_t)N_NODES * OUT_TOT]; // 51.2 MB
__device__ __align__(16) float g_el[N_NODES * 4];
__device__ __align__(16) float g_er[N_NODES * 4];
__device__ __align__(16) float g_csr_e[(size_t)N_EDGES * 4];          // 25.6 MB
__device__ int g_csr_src[N_EDGES];
__device__ int g_deg[N_NODES];
__device__ int g_row_ptr[N_NODES + 1];
__device__ int g_cursor[N_NODES];

// ---------------- helpers ------------------------------------------------------
__device__ __forceinline__ u32 pack_bf16(float a, float b) {
    __nv_bfloat162 t = __floats2bfloat162_rn(a, b);
    return *(u32*)&t;
}
// hi-halves of two fp32 -> packed bf16x2 (truncation split)
__device__ __forceinline__ u32 pack_hi(u32 ax, u32 ay) {
    u32 r;
    asm("prmt.b32 %0, %1, %2, 0x7632;" : "=r"(r) : "r"(ax), "r"(ay));
    return r;
}

#define MMA_BF16(c, a0, a1, a2, a3, b0, b1)                                     \
    asm volatile("mma.sync.aligned.m16n8k16.row.col.f32.bf16.bf16.f32 "         \
                 "{%0,%1,%2,%3}, {%4,%5,%6,%7}, {%8,%9}, {%0,%1,%2,%3};"        \
                 : "+f"((c)[0]), "+f"((c)[1]), "+f"((c)[2]), "+f"((c)[3])       \
                 : "r"(a0), "r"(a1), "r"(a2), "r"(a3), "r"(b0), "r"(b1))

// ---------------- 0: zero degree histogram -------------------------------------
__global__ void zero_deg_kernel() {
    int i = blockIdx.x * blockDim.x + threadIdx.x;
    if (i < N_NODES) g_deg[i] = 0;
}

// ---------------- 1: degree histogram -------------------------------------------
__global__ void deg_hist_kernel(const int* __restrict__ dst) {
    int e = blockIdx.x * blockDim.x + threadIdx.x;
    if (e < N_EDGES) atomicAdd(&g_deg[dst[e]], 1);
}

// ---------------- 2: projection GEMM (split-bf16 MMA) + fused el/er epilogue ----
__global__ __launch_bounds__(256, 2) void gemm_mma_kernel(const float* __restrict__ A,
                                                          const float* __restrict__ W,
                                                          const float* __restrict__ attn_l,
                                                          const float* __restrict__ attn_r) {
    __shared__ u32 Ah[128][20], Al[128][20], Bh[128][20], Bl[128][20];

    const int tid  = threadIdx.x;
    const int bm   = blockIdx.x * 128;
    const int lane = tid & 31;
    const int w    = tid >> 5;
    const int wr   = w >> 1;        // 0..3 (row tile of 32)
    const int wc   = w & 1;         // 0..1 (col tile of 64)
    const int g    = lane >> 2;     // 0..7
    const int tg   = lane & 3;      // 0..3

    float acc[2][8][4];
#pragma unroll
    for (int rt = 0; rt < 2; rt++)
#pragma unroll
        for (int nt = 0; nt < 8; nt++)
#pragma unroll
            for (int q = 0; q < 4; q++) acc[rt][nt][q] = 0.0f;

    for (int k0 = 0; k0 < IN_F; k0 += 32) {
#pragma unroll
        for (int l = 0; l < 4; l++) {
            int idx = tid + l * 256;       // 0..1023
            int r   = idx >> 3;            // 0..127
            int kq  = (idx & 7) * 4;       // 0..28
            int grow = bm + r;
            float4 av = (grow < N_NODES)
                ? *(const float4*)&A[(size_t)grow * IN_F + k0 + kq]
                : make_float4(0.f, 0.f, 0.f, 0.f);
            u32 ax = __float_as_uint(av.x), ay = __float_as_uint(av.y);
            u32 az = __float_as_uint(av.z), aw = __float_as_uint(av.w);
            Ah[r][(kq >> 1) + 0] = pack_hi(ax, ay);
            Ah[r][(kq >> 1) + 1] = pack_hi(az, aw);
            Al[r][(kq >> 1) + 0] = pack_bf16(av.x - __uint_as_float(ax & 0xFFFF0000u),
                                             av.y - __uint_as_float(ay & 0xFFFF0000u));
            Al[r][(kq >> 1) + 1] = pack_bf16(av.z - __uint_as_float(az & 0xFFFF0000u),
                                             av.w - __uint_as_float(aw & 0xFFFF0000u));

            float4 bv = *(const float4*)&W[(size_t)r * IN_F + k0 + kq];
            u32 bx = __float_as_uint(bv.x), by = __float_as_uint(bv.y);
            u32 bz = __float_as_uint(bv.z), bw = __float_as_uint(bv.w);
            Bh[r][(kq >> 1) + 0] = pack_hi(bx, by);
            Bh[r][(kq >> 1) + 1] = pack_hi(bz, bw);
            Bl[r][(kq >> 1) + 0] = pack_bf16(bv.x - __uint_as_float(bx & 0xFFFF0000u),
                                             bv.y - __uint_as_float(by & 0xFFFF0000u));
            Bl[r][(kq >> 1) + 1] = pack_bf16(bv.z - __uint_as_float(bz & 0xFFFF0000u),
                                             bv.w - __uint_as_float(bw & 0xFFFF0000u));
        }
        __syncthreads();

#pragma unroll
        for (int ks = 0; ks < 2; ks++) {
            int kb = ks * 8 + tg;     // uint32 col of fragment pair
#pragma unroll
            for (int rt = 0; rt < 2; rt++) {
                int rb = wr * 32 + rt * 16;
                u32 ah0 = Ah[rb + g    ][kb    ];
                u32 ah1 = Ah[rb + g + 8][kb    ];
                u32 ah2 = Ah[rb + g    ][kb + 4];
                u32 ah3 = Ah[rb + g + 8][kb + 4];
                u32 al0 = Al[rb + g    ][kb    ];
                u32 al1 = Al[rb + g + 8][kb    ];
                u32 al2 = Al[rb + g    ][kb + 4];
                u32 al3 = Al[rb + g + 8][kb + 4];
#pragma unroll
                for (int nt = 0; nt < 8; nt++) {
                    int nb = wc * 64 + nt * 8;
                    u32 bh0 = Bh[nb + g][kb    ];
                    u32 bh1 = Bh[nb + g][kb + 4];
                    u32 bl0 = Bl[nb + g][kb    ];
                    u32 bl1 = Bl[nb + g][kb + 4];
                    float* c = acc[rt][nt];
                    MMA_BF16(c, ah0, ah1, ah2, ah3, bh0, bh1);
                    MMA_BF16(c, ah0, ah1, ah2, ah3, bl0, bl1);
                    MMA_BF16(c, al0, al1, al2, al3, bh0, bh1);
                }
            }
        }
        __syncthreads();
    }

    // ---- epilogue 1: store feat_src tile ----
#pragma unroll
    for (int rt = 0; rt < 2; rt++) {
        int r0 = bm + wr * 32 + rt * 16 + g;
#pragma unroll
        for (int nt = 0; nt < 8; nt++) {
            int cc = wc * 64 + nt * 8 + tg * 2;
            if (r0 < N_NODES)
                *(float2*)&g_feat_src[(size_t)r0 * OUT_TOT + cc] =
                    make_float2(acc[rt][nt][0], acc[rt][nt][1]);
            if (r0 + 8 < N_NODES)
                *(float2*)&g_feat_src[(size_t)(r0 + 8) * OUT_TOT + cc] =
                    make_float2(acc[rt][nt][2], acc[rt][nt][3]);
        }
    }

    // ---- epilogue 2: fused el/er = dot(feat_src_row, attn) ----
    // thread owns cols wc*64+nt*8+tg*2 (+1); nt 0..3 -> head wc*2, nt 4..7 -> head wc*2+1
    float el_a[2][2][2] = {};  // [rt][rowoff][headhalf]
    float er_a[2][2][2] = {};
#pragma unroll
    for (int nt = 0; nt < 8; nt++) {
        int cc = wc * 64 + nt * 8 + tg * 2;
        float2 alv = *(const float2*)&attn_l[cc];
        float2 arv = *(const float2*)&attn_r[cc];
        int hh = nt >> 2;
#pragma unroll
        for (int rt = 0; rt < 2; rt++) {
            el_a[rt][0][hh] += acc[rt][nt][0] * alv.x + acc[rt][nt][1] * alv.y;
            el_a[rt][1][hh] += acc[rt][nt][2] * alv.x + acc[rt][nt][3] * alv.y;
            er_a[rt][0][hh] += acc[rt][nt][0] * arv.x + acc[rt][nt][1] * arv.y;
            er_a[rt][1][hh] += acc[rt][nt][2] * arv.x + acc[rt][nt][3] * arv.y;
        }
    }
#pragma unroll
    for (int rt = 0; rt < 2; rt++)
#pragma unroll
        for (int ro = 0; ro < 2; ro++)
#pragma unroll
            for (int hh = 0; hh < 2; hh++) {
                el_a[rt][ro][hh] += __shfl_xor_sync(0xffffffffu, el_a[rt][ro][hh], 1);
                el_a[rt][ro][hh] += __shfl_xor_sync(0xffffffffu, el_a[rt][ro][hh], 2);
                er_a[rt][ro][hh] += __shfl_xor_sync(0xffffffffu, er_a[rt][ro][hh], 1);
                er_a[rt][ro][hh] += __shfl_xor_sync(0xffffffffu, er_a[rt][ro][hh], 2);
            }
    if (tg == 0) {
#pragma unroll
        for (int rt = 0; rt < 2; rt++) {
            int r0 = bm + wr * 32 + rt * 16 + g;
#pragma unroll
            for (int ro = 0; ro < 2; ro++) {
                int row = r0 + ro * 8;
                if (row < N_NODES) {
#pragma unroll
                    for (int hh = 0; hh < 2; hh++) {
                        int head = wc * 2 + hh;
                        g_el[row * 4 + head] = el_a[rt][ro][hh];
                        g_er[row * 4 + head] = er_a[rt][ro][hh];
                    }
                }
            }
        }
    }
}

// ---------------- 3: single-block exclusive scan -> row_ptr, cursor ------------
__global__ __launch_bounds__(1024) void scan_kernel() {
    __shared__ int ssum[1024];
    const int CHUNK = 100;            // 1000 active threads cover 100000 nodes
    int t = threadIdx.x;
    int base = t * CHUNK;
    int s = 0;
    if (base < N_NODES) {
        const int4* p = (const int4*)&g_deg[base];
#pragma unroll
        for (int j = 0; j < CHUNK / 4; j++) {
            int4 v = p[j];
            s += v.x + v.y + v.z + v.w;
        }
    }
    ssum[t] = s;
    __syncthreads();
    for (int off = 1; off < 1024; off <<= 1) {
        int v = (t >= off) ? ssum[t - off] : 0;
        __syncthreads();
        ssum[t] += v;
        __syncthreads();
    }
    if (base < N_NODES) {
        int run = ssum[t] - s;   // exclusive prefix of this chunk
        for (int j = 0; j < CHUNK; j++) {
            int idx = base + j;
            g_row_ptr[idx] = run;
            g_cursor[idx]  = run;
            run += g_deg[idx];
        }
    }
    if (t == 1023) g_row_ptr[N_NODES] = ssum[1023];
}

// ---------------- 4: fused edge logits + LeakyReLU + CSR scatter ----------------
__global__ void edge_scatter_kernel(const int* __restrict__ src, const int* __restrict__ dst,
                                    const float* __restrict__ e_w,
                                    const float* __restrict__ attn_ew) {
    int e = blockIdx.x * blockDim.x + threadIdx.x;
    if (e >= N_EDGES) return;
    int s = src[e], d = dst[e];
    float4 l  = ((const float4*)g_el)[s];
    float4 r  = ((const float4*)g_er)[d];
    float4 w0 = *(const float4*)&e_w[(size_t)e * 8];
    float4 w1 = *(const float4*)&e_w[(size_t)e * 8 + 4];
    float4 a0 = *(const float4*)&attn_ew[0];
    float4 a1 = *(const float4*)&attn_ew[4];
    float v0 = l.x + r.x + w0.x * a0.x + w0.y * a0.y;
    float v1 = l.y + r.y + w0.z * a0.z + w0.w * a0.w;
    float v2 = l.z + r.z + w1.x * a1.x + w1.y * a1.y;
    float v3 = l.w + r.w + w1.z * a1.z + w1.w * a1.w;
    v0 = v0 > 0.f ? v0 : NEG_SLOPE * v0;
    v1 = v1 > 0.f ? v1 : NEG_SLOPE * v1;
    v2 = v2 > 0.f ? v2 : NEG_SLOPE * v2;
    v3 = v3 > 0.f ? v3 : NEG_SLOPE * v3;
    int pos = atomicAdd(&g_cursor[d], 1);
    g_csr_src[pos] = s;
    ((float4*)g_csr_e)[pos] = make_float4(v0, v1, v2, v3);
}

// ---------------- 5: warp-per-node softmax + weighted aggregation + ELU ---------
// Lane l owns output columns [4l, 4l+4) => head = l>>3. One LDG.128 per edge/warp.
__global__ __launch_bounds__(256) void aggregate_kernel(float* __restrict__ out) {
    __shared__ float sp[8][128];   // per-warp: 32 edges x 4 heads of exp(e-m)
    __shared__ int   ssrc[8][32];
    int gw   = (blockIdx.x * blockDim.x + threadIdx.x) >> 5;
    int lane = threadIdx.x & 31;
    int wl   = threadIdx.x >> 5;
    if (gw >= N_NODES) return;
    int beg = g_row_ptr[gw], end = g_row_ptr[gw + 1];
    int head = lane >> 3;

    // pass 1: per-head max
    float m0 = -1e30f, m1 = -1e30f, m2 = -1e30f, m3 = -1e30f;
    for (int i = beg + lane; i < end; i += 32) {
        float4 ev = ((const float4*)g_csr_e)[i];
        m0 = fmaxf(m0, ev.x); m1 = fmaxf(m1, ev.y);
        m2 = fmaxf(m2, ev.z); m3 = fmaxf(m3, ev.w);
    }
#pragma unroll
    for (int off = 16; off; off >>= 1) {
        m0 = fmaxf(m0, __shfl_xor_sync(0xffffffffu, m0, off));
        m1 = fmaxf(m1, __shfl_xor_sync(0xffffffffu, m1, off));
        m2 = fmaxf(m2, __shfl_xor_sync(0xffffffffu, m2, off));
        m3 = fmaxf(m3, __shfl_xor_sync(0xffffffffu, m3, off));
    }

    // pass 2: unnormalized exp into smem; gather full feat row per edge (LDG.128)
    float s0 = 0.f, s1 = 0.f, s2 = 0.f, s3 = 0.f;
    float4 a = make_float4(0.f, 0.f, 0.f, 0.f);
    for (int c = beg; c < end; c += 32) {
        int i = c + lane;
        float4 p = make_float4(0.f, 0.f, 0.f, 0.f);
        if (i < end) {
            float4 ev = ((const float4*)g_csr_e)[i];
            p.x = __expf(ev.x - m0); p.y = __expf(ev.y - m1);
            p.z = __expf(ev.z - m2); p.w = __expf(ev.w - m3);
            s0 += p.x; s1 += p.y; s2 += p.z; s3 += p.w;
            ssrc[wl][lane] = g_csr_src[i];
        }
        ((float4*)sp[wl])[lane] = p;
        __syncwarp();
        int cnt = min(32, end - c);
#pragma unroll 4
        for (int j = 0; j < cnt; j++) {
            float4 fr = *(const float4*)&g_feat_src[(size_t)ssrc[wl][j] * OUT_TOT + lane * 4];
            float wgt = sp[wl][j * 4 + head];
            a.x += fr.x * wgt; a.y += fr.y * wgt;
            a.z += fr.z * wgt; a.w += fr.w * wgt;
        }
        __syncwarp();
    }
#pragma unroll
    for (int off = 16; off; off >>= 1) {
        s0 += __shfl_xor_sync(0xffffffffu, s0, off);
        s1 += __shfl_xor_sync(0xffffffffu, s1, off);
        s2 += __shfl_xor_sync(0xffffffffu, s2, off);
        s3 += __shfl_xor_sync(0xffffffffu, s3, off);
    }
    float invs;
    if      (head == 0) invs = s0 > 0.f ? 1.f / s0 : 0.f;
    else if (head == 1) invs = s1 > 0.f ? 1.f / s1 : 0.f;
    else if (head == 2) invs = s2 > 0.f ? 1.f / s2 : 0.f;
    else                invs = s3 > 0.f ? 1.f / s3 : 0.f;
    a.x *= invs; a.y *= invs; a.z *= invs; a.w *= invs;

    a.x = a.x > 0.f ? a.x : expm1f(a.x);
    a.y = a.y > 0.f ? a.y : expm1f(a.y);
    a.z = a.z > 0.f ? a.z : expm1f(a.z);
    a.w = a.w > 0.f ? a.w : expm1f(a.w);
    *(float4*)&out[(size_t)gw * OUT_TOT + lane * 4] = a;
}

// ---------------- launch --------------------------------------------------------
extern "C" void kernel_launch(void* const* d_in, const int* in_sizes, int n_in,
                              void* d_out, int out_size) {
    const float* feat    = (const float*)d_in[0];
    const float* e_w     = (const float*)d_in[1];
    const int*   src     = (const int*)  d_in[2];
    const int*   dst     = (const int*)  d_in[3];
    const float* W_fc    = (const float*)d_in[4];
    const float* attn_l  = (const float*)d_in[5];
    const float* attn_r  = (const float*)d_in[6];
    const float* attn_ew = (const float*)d_in[7];
    float* out = (float*)d_out;

    zero_deg_kernel<<<(N_NODES + 255) / 256, 256>>>();
    deg_hist_kernel<<<(N_EDGES + 255) / 256, 256>>>(dst);
    gemm_mma_kernel<<<(N_NODES + 127) / 128, 256>>>(feat, W_fc, attn_l, attn_r);
    scan_kernel<<<1, 1024>>>();
    edge_scatter_kernel<<<(N_EDGES + 255) / 256, 256>>>(src, dst, e_w, attn_ew);
    aggregate_kernel<<<((N_NODES * 32) + 255) / 256, 256>>>(out);
}

// round 5
// speedup vs baseline: 2.4049x; 1.6572x over previous
#include <cuda_runtime.h>
#include <cuda_bf16.h>
#include <stdint.h>
#include <math.h>

typedef unsigned int u32;

#define N_NODES   100000
#define N_EDGES   1600000
#define IN_F      256
#define OUT_TOT   128          // 4 heads * 32 feats
#define NEG_SLOPE 0.2f

#define SCAN_TILE 1024
#define SCAN_NBLK ((N_NODES + SCAN_TILE - 1) / SCAN_TILE)   // 98

// ---------------- scratch (static device memory; no allocations) -------------
__device__ __align__(16) float g_feat_src[(size_t)N_NODES * OUT_TOT]; // 51.2 MB
__device__ __align__(16) float g_el[N_NODES * 4];
__device__ __align__(16) float g_er[N_NODES * 4];
__device__ __align__(16) float g_csr_e[(size_t)N_EDGES * 4];          // 25.6 MB
__device__ int g_csr_src[N_EDGES];
__device__ __align__(16) int g_deg[N_NODES];
__device__ __align__(16) int g_row_ptr[N_NODES + 4];
__device__ __align__(16) int g_cursor[N_NODES];
__device__ int g_block_sum[SCAN_NBLK];
__device__ int g_block_off[SCAN_NBLK + 1];

// ---------------- helpers ------------------------------------------------------
__device__ __forceinline__ u32 pack_bf16(float a, float b) {
    __nv_bfloat162 t = __floats2bfloat162_rn(a, b);
    return *(u32*)&t;
}
// hi-halves of two fp32 -> packed bf16x2 (truncation split)
__device__ __forceinline__ u32 pack_hi(u32 ax, u32 ay) {
    u32 r;
    asm("prmt.b32 %0, %1, %2, 0x7632;" : "=r"(r) : "r"(ax), "r"(ay));
    return r;
}

#define MMA_BF16(c, a0, a1, a2, a3, b0, b1)                                     \
    asm volatile("mma.sync.aligned.m16n8k16.row.col.f32.bf16.bf16.f32 "         \
                 "{%0,%1,%2,%3}, {%4,%5,%6,%7}, {%8,%9}, {%0,%1,%2,%3};"        \
                 : "+f"((c)[0]), "+f"((c)[1]), "+f"((c)[2]), "+f"((c)[3])       \
                 : "r"(a0), "r"(a1), "r"(a2), "r"(a3), "r"(b0), "r"(b1))

// ---------------- 0: zero degree histogram -------------------------------------
__global__ void zero_deg_kernel() {
    int i = blockIdx.x * blockDim.x + threadIdx.x;
    if (i < N_NODES) g_deg[i] = 0;
}

// ---------------- 1: degree histogram -------------------------------------------
__global__ void deg_hist_kernel(const int* __restrict__ dst) {
    int e = blockIdx.x * blockDim.x + threadIdx.x;
    if (e < N_EDGES) atomicAdd(&g_deg[dst[e]], 1);
}

// ---------------- 2: projection GEMM (split-bf16 MMA) + fused el/er epilogue ----
__global__ __launch_bounds__(256, 2) void gemm_mma_kernel(const float* __restrict__ A,
                                                          const float* __restrict__ W,
                                                          const float* __restrict__ attn_l,
                                                          const float* __restrict__ attn_r) {
    __shared__ u32 Ah[128][20], Al[128][20], Bh[128][20], Bl[128][20];

    const int tid  = threadIdx.x;
    const int bm   = blockIdx.x * 128;
    const int lane = tid & 31;
    const int w    = tid >> 5;
    const int wr   = w >> 1;        // 0..3 (row tile of 32)
    const int wc   = w & 1;         // 0..1 (col tile of 64)
    const int g    = lane >> 2;     // 0..7
    const int tg   = lane & 3;      // 0..3

    float acc[2][8][4];
#pragma unroll
    for (int rt = 0; rt < 2; rt++)
#pragma unroll
        for (int nt = 0; nt < 8; nt++)
#pragma unroll
            for (int q = 0; q < 4; q++) acc[rt][nt][q] = 0.0f;

    for (int k0 = 0; k0 < IN_F; k0 += 32) {
#pragma unroll
        for (int l = 0; l < 4; l++) {
            int idx = tid + l * 256;       // 0..1023
            int r   = idx >> 3;            // 0..127
            int kq  = (idx & 7) * 4;       // 0..28
            int grow = bm + r;
            float4 av = (grow < N_NODES)
                ? *(const float4*)&A[(size_t)grow * IN_F + k0 + kq]
                : make_float4(0.f, 0.f, 0.f, 0.f);
            u32 ax = __float_as_uint(av.x), ay = __float_as_uint(av.y);
            u32 az = __float_as_uint(av.z), aw = __float_as_uint(av.w);
            Ah[r][(kq >> 1) + 0] = pack_hi(ax, ay);
            Ah[r][(kq >> 1) + 1] = pack_hi(az, aw);
            Al[r][(kq >> 1) + 0] = pack_bf16(av.x - __uint_as_float(ax & 0xFFFF0000u),
                                             av.y - __uint_as_float(ay & 0xFFFF0000u));
            Al[r][(kq >> 1) + 1] = pack_bf16(av.z - __uint_as_float(az & 0xFFFF0000u),
                                             av.w - __uint_as_float(aw & 0xFFFF0000u));

            float4 bv = *(const float4*)&W[(size_t)r * IN_F + k0 + kq];
            u32 bx = __float_as_uint(bv.x), by = __float_as_uint(bv.y);
            u32 bz = __float_as_uint(bv.z), bw = __float_as_uint(bv.w);
            Bh[r][(kq >> 1) + 0] = pack_hi(bx, by);
            Bh[r][(kq >> 1) + 1] = pack_hi(bz, bw);
            Bl[r][(kq >> 1) + 0] = pack_bf16(bv.x - __uint_as_float(bx & 0xFFFF0000u),
                                             bv.y - __uint_as_float(by & 0xFFFF0000u));
            Bl[r][(kq >> 1) + 1] = pack_bf16(bv.z - __uint_as_float(bz & 0xFFFF0000u),
                                             bv.w - __uint_as_float(bw & 0xFFFF0000u));
        }
        __syncthreads();

#pragma unroll
        for (int ks = 0; ks < 2; ks++) {
            int kb = ks * 8 + tg;     // uint32 col of fragment pair
#pragma unroll
            for (int rt = 0; rt < 2; rt++) {
                int rb = wr * 32 + rt * 16;
                u32 ah0 = Ah[rb + g    ][kb    ];
                u32 ah1 = Ah[rb + g + 8][kb    ];
                u32 ah2 = Ah[rb + g    ][kb + 4];
                u32 ah3 = Ah[rb + g + 8][kb + 4];
                u32 al0 = Al[rb + g    ][kb    ];
                u32 al1 = Al[rb + g + 8][kb    ];
                u32 al2 = Al[rb + g    ][kb + 4];
                u32 al3 = Al[rb + g + 8][kb + 4];
#pragma unroll
                for (int nt = 0; nt < 8; nt++) {
                    int nb = wc * 64 + nt * 8;
                    u32 bh0 = Bh[nb + g][kb    ];
                    u32 bh1 = Bh[nb + g][kb + 4];
                    u32 bl0 = Bl[nb + g][kb    ];
                    u32 bl1 = Bl[nb + g][kb + 4];
                    float* c = acc[rt][nt];
                    MMA_BF16(c, ah0, ah1, ah2, ah3, bh0, bh1);
                    MMA_BF16(c, ah0, ah1, ah2, ah3, bl0, bl1);
                    MMA_BF16(c, al0, al1, al2, al3, bh0, bh1);
                }
            }
        }
        __syncthreads();
    }

    // ---- epilogue 1: store feat_src tile ----
#pragma unroll
    for (int rt = 0; rt < 2; rt++) {
        int r0 = bm + wr * 32 + rt * 16 + g;
#pragma unroll
        for (int nt = 0; nt < 8; nt++) {
            int cc = wc * 64 + nt * 8 + tg * 2;
            if (r0 < N_NODES)
                *(float2*)&g_feat_src[(size_t)r0 * OUT_TOT + cc] =
                    make_float2(acc[rt][nt][0], acc[rt][nt][1]);
            if (r0 + 8 < N_NODES)
                *(float2*)&g_feat_src[(size_t)(r0 + 8) * OUT_TOT + cc] =
                    make_float2(acc[rt][nt][2], acc[rt][nt][3]);
        }
    }

    // ---- epilogue 2: fused el/er = dot(feat_src_row, attn) ----
    float el_a[2][2][2] = {};  // [rt][rowoff][headhalf]
    float er_a[2][2][2] = {};
#pragma unroll
    for (int nt = 0; nt < 8; nt++) {
        int cc = wc * 64 + nt * 8 + tg * 2;
        float2 alv = *(const float2*)&attn_l[cc];
        float2 arv = *(const float2*)&attn_r[cc];
        int hh = nt >> 2;
#pragma unroll
        for (int rt = 0; rt < 2; rt++) {
            el_a[rt][0][hh] += acc[rt][nt][0] * alv.x + acc[rt][nt][1] * alv.y;
            el_a[rt][1][hh] += acc[rt][nt][2] * alv.x + acc[rt][nt][3] * alv.y;
            er_a[rt][0][hh] += acc[rt][nt][0] * arv.x + acc[rt][nt][1] * arv.y;
            er_a[rt][1][hh] += acc[rt][nt][2] * arv.x + acc[rt][nt][3] * arv.y;
        }
    }
#pragma unroll
    for (int rt = 0; rt < 2; rt++)
#pragma unroll
        for (int ro = 0; ro < 2; ro++)
#pragma unroll
            for (int hh = 0; hh < 2; hh++) {
                el_a[rt][ro][hh] += __shfl_xor_sync(0xffffffffu, el_a[rt][ro][hh], 1);
                el_a[rt][ro][hh] += __shfl_xor_sync(0xffffffffu, el_a[rt][ro][hh], 2);
                er_a[rt][ro][hh] += __shfl_xor_sync(0xffffffffu, er_a[rt][ro][hh], 1);
                er_a[rt][ro][hh] += __shfl_xor_sync(0xffffffffu, er_a[rt][ro][hh], 2);
            }
    if (tg == 0) {
#pragma unroll
        for (int rt = 0; rt < 2; rt++) {
            int r0 = bm + wr * 32 + rt * 16 + g;
#pragma unroll
            for (int ro = 0; ro < 2; ro++) {
                int row = r0 + ro * 8;
                if (row < N_NODES) {
#pragma unroll
                    for (int hh = 0; hh < 2; hh++) {
                        int head = wc * 2 + hh;
                        g_el[row * 4 + head] = el_a[rt][ro][hh];
                        g_er[row * 4 + head] = er_a[rt][ro][hh];
                    }
                }
            }
        }
    }
}

// ---------------- 3a: per-tile degree sums (98 blocks x 256 thr, int4) ----------
__global__ __launch_bounds__(256) void scan_block_sums() {
    __shared__ int red[256];
    int b = blockIdx.x, t = threadIdx.x;
    int base = b * SCAN_TILE + t * 4;
    int s = 0;
    if (base < N_NODES) {
        int4 v = *(const int4*)&g_deg[base];
        s = v.x + v.y + v.z + v.w;
    }
    red[t] = s;
    __syncthreads();
#pragma unroll
    for (int off = 128; off; off >>= 1) {
        if (t < off) red[t] += red[t + off];
        __syncthreads();
    }
    if (t == 0) g_block_sum[b] = red[0];
}

// ---------------- 3b: scan the 98 block sums (1 tiny block) ---------------------
__global__ __launch_bounds__(128) void scan_offsets() {
    __shared__ int ss[128];
    int t = threadIdx.x;
    int v = (t < SCAN_NBLK) ? g_block_sum[t] : 0;
    ss[t] = v;
    __syncthreads();
#pragma unroll
    for (int off = 1; off < 128; off <<= 1) {
        int tmp = (t >= off) ? ss[t - off] : 0;
        __syncthreads();
        ss[t] += tmp;
        __syncthreads();
    }
    if (t < SCAN_NBLK) g_block_off[t] = ss[t] - v;   // exclusive
    if (t == SCAN_NBLK - 1) g_block_off[SCAN_NBLK] = ss[t];
}

// ---------------- 3c: write row_ptr + cursor (98 blocks) ------------------------
__global__ __launch_bounds__(256) void scan_write() {
    __shared__ int ss[256];
    int b = blockIdx.x, t = threadIdx.x;
    int base = b * SCAN_TILE + t * 4;
    int4 v = make_int4(0, 0, 0, 0);
    if (base < N_NODES) v = *(const int4*)&g_deg[base];
    int ts = v.x + v.y + v.z + v.w;
    ss[t] = ts;
    __syncthreads();
#pragma unroll
    for (int off = 1; off < 256; off <<= 1) {
        int tmp = (t >= off) ? ss[t - off] : 0;
        __syncthreads();
        ss[t] += tmp;
        __syncthreads();
    }
    if (base < N_NODES) {
        int r0 = g_block_off[b] + ss[t] - ts;
        int r1 = r0 + v.x, r2 = r1 + v.y, r3 = r2 + v.z;
        *(int4*)&g_row_ptr[base] = make_int4(r0, r1, r2, r3);
        *(int4*)&g_cursor[base]  = make_int4(r0, r1, r2, r3);
    }
    if (b == 0 && t == 0) g_row_ptr[N_NODES] = g_block_off[SCAN_NBLK];
}

// ---------------- 4: fused edge logits + LeakyReLU + CSR scatter ----------------
__global__ void edge_scatter_kernel(const int* __restrict__ src, const int* __restrict__ dst,
                                    const float* __restrict__ e_w,
                                    const float* __restrict__ attn_ew) {
    int e = blockIdx.x * blockDim.x + threadIdx.x;
    if (e >= N_EDGES) return;
    int s = src[e], d = dst[e];
    float4 l  = ((const float4*)g_el)[s];
    float4 r  = ((const float4*)g_er)[d];
    float4 w0 = *(const float4*)&e_w[(size_t)e * 8];
    float4 w1 = *(const float4*)&e_w[(size_t)e * 8 + 4];
    float4 a0 = *(const float4*)&attn_ew[0];
    float4 a1 = *(const float4*)&attn_ew[4];
    float v0 = l.x + r.x + w0.x * a0.x + w0.y * a0.y;
    float v1 = l.y + r.y + w0.z * a0.z + w0.w * a0.w;
    float v2 = l.z + r.z + w1.x * a1.x + w1.y * a1.y;
    float v3 = l.w + r.w + w1.z * a1.z + w1.w * a1.w;
    v0 = v0 > 0.f ? v0 : NEG_SLOPE * v0;
    v1 = v1 > 0.f ? v1 : NEG_SLOPE * v1;
    v2 = v2 > 0.f ? v2 : NEG_SLOPE * v2;
    v3 = v3 > 0.f ? v3 : NEG_SLOPE * v3;
    int pos = atomicAdd(&g_cursor[d], 1);
    g_csr_src[pos] = s;
    ((float4*)g_csr_e)[pos] = make_float4(v0, v1, v2, v3);
}

// ---------------- 5: warp-per-node softmax + weighted aggregation + ELU ---------
__global__ __launch_bounds__(256) void aggregate_kernel(float* __restrict__ out) {
    __shared__ float sp[8][128];
    __shared__ int   ssrc[8][32];
    int gw   = (blockIdx.x * blockDim.x + threadIdx.x) >> 5;
    int lane = threadIdx.x & 31;
    int wl   = threadIdx.x >> 5;
    if (gw >= N_NODES) return;
    int beg = g_row_ptr[gw], end = g_row_ptr[gw + 1];
    int head = lane >> 3;

    float m0 = -1e30f, m1 = -1e30f, m2 = -1e30f, m3 = -1e30f;
    for (int i = beg + lane; i < end; i += 32) {
        float4 ev = ((const float4*)g_csr_e)[i];
        m0 = fmaxf(m0, ev.x); m1 = fmaxf(m1, ev.y);
        m2 = fmaxf(m2, ev.z); m3 = fmaxf(m3, ev.w);
    }
#pragma unroll
    for (int off = 16; off; off >>= 1) {
        m0 = fmaxf(m0, __shfl_xor_sync(0xffffffffu, m0, off));
        m1 = fmaxf(m1, __shfl_xor_sync(0xffffffffu, m1, off));
        m2 = fmaxf(m2, __shfl_xor_sync(0xffffffffu, m2, off));
        m3 = fmaxf(m3, __shfl_xor_sync(0xffffffffu, m3, off));
    }

    float s0 = 0.f, s1 = 0.f, s2 = 0.f, s3 = 0.f;
    float4 a = make_float4(0.f, 0.f, 0.f, 0.f);
    for (int c = beg; c < end; c += 32) {
        int i = c + lane;
        float4 p = make_float4(0.f, 0.f, 0.f, 0.f);
        if (i < end) {
            float4 ev = ((const float4*)g_csr_e)[i];
            p.x = __expf(ev.x - m0); p.y = __expf(ev.y - m1);
            p.z = __expf(ev.z - m2); p.w = __expf(ev.w - m3);
            s0 += p.x; s1 += p.y; s2 += p.z; s3 += p.w;
            ssrc[wl][lane] = g_csr_src[i];
        }
        ((float4*)sp[wl])[lane] = p;
        __syncwarp();
        int cnt = min(32, end - c);
#pragma unroll 4
        for (int j = 0; j < cnt; j++) {
            float4 fr = *(const float4*)&g_feat_src[(size_t)ssrc[wl][j] * OUT_TOT + lane * 4];
            float wgt = sp[wl][j * 4 + head];
            a.x += fr.x * wgt; a.y += fr.y * wgt;
            a.z += fr.z * wgt; a.w += fr.w * wgt;
        }
        __syncwarp();
    }
#pragma unroll
    for (int off = 16; off; off >>= 1) {
        s0 += __shfl_xor_sync(0xffffffffu, s0, off);
        s1 += __shfl_xor_sync(0xffffffffu, s1, off);
        s2 += __shfl_xor_sync(0xffffffffu, s2, off);
        s3 += __shfl_xor_sync(0xffffffffu, s3, off);
    }
    float invs;
    if      (head == 0) invs = s0 > 0.f ? 1.f / s0 : 0.f;
    else if (head == 1) invs = s1 > 0.f ? 1.f / s1 : 0.f;
    else if (head == 2) invs = s2 > 0.f ? 1.f / s2 : 0.f;
    else                invs = s3 > 0.f ? 1.f / s3 : 0.f;
    a.x *= invs; a.y *= invs; a.z *= invs; a.w *= invs;

    a.x = a.x > 0.f ? a.x : expm1f(a.x);
    a.y = a.y > 0.f ? a.y : expm1f(a.y);
    a.z = a.z > 0.f ? a.z : expm1f(a.z);
    a.w = a.w > 0.f ? a.w : expm1f(a.w);
    *(float4*)&out[(size_t)gw * OUT_TOT + lane * 4] = a;
}

// ---------------- launch --------------------------------------------------------
extern "C" void kernel_launch(void* const* d_in, const int* in_sizes, int n_in,
                              void* d_out, int out_size) {
    const float* feat    = (const float*)d_in[0];
    const float* e_w     = (const float*)d_in[1];
    const int*   src     = (const int*)  d_in[2];
    const int*   dst     = (const int*)  d_in[3];
    const float* W_fc    = (const float*)d_in[4];
    const float* attn_l  = (const float*)d_in[5];
    const float* attn_r  = (const float*)d_in[6];
    const float* attn_ew = (const float*)d_in[7];
    float* out = (float*)d_out;

    zero_deg_kernel<<<(N_NODES + 255) / 256, 256>>>();
    deg_hist_kernel<<<(N_EDGES + 255) / 256, 256>>>(dst);
    gemm_mma_kernel<<<(N_NODES + 127) / 128, 256>>>(feat, W_fc, attn_l, attn_r);
    scan_block_sums<<<SCAN_NBLK, 256>>>();
    scan_offsets<<<1, 128>>>();
    scan_write<<<SCAN_NBLK, 256>>>();
    edge_scatter_kernel<<<(N_EDGES + 255) / 256, 256>>>(src, dst, e_w, attn_ew);
    aggregate_kernel<<<((N_NODES * 32) + 255) / 256, 256>>>(out);
}